// round 6
// baseline (speedup 1.0000x reference)
#include <cuda_runtime.h>
#include <cstdint>
#include <math_constants.h>

#define B      128
#define HH     400
#define WW     400
#define HW     160000
#define WPR    13            // 32-bit words per row
#define NWORDS 5200          // 400 * 13
#define NA     2500
#define NP     20000
#define NI     (HW - NP)
#define CAND_CAP 8192
#define CPB    10            // chunks per batch (each = 40 rows, disjoint)
#define CHUNK  (HW / CPB)    // 16000 elements
#define CH4    (CHUNK / 4)   // 4000 float4
#define RPC    (HH / CPB)    // 40 rows per chunk
#define SLICE  (RPC * WPR)   // 520 words per chunk slice

// Output layout: flat f32 concat of (out_idx, query_pos, new_mask, xy_vox_idx, ignore_idx)
#define OI_OFF 0l
#define QP_OFF 2560000l
#define NM_OFF 33280000l
#define XY_OFF 53760000l
#define IG_OFF 58880000l

__device__ uint32_t g_k16[(size_t)B * HW / 2];       // packed 16-bit keys, 41 MB
__device__ uint32_t g_histc[B][CPB][2048];           // per-chunk histograms, 10.5 MB
__device__ uint2    g_pivot[B];                      // {p1, rem}
__device__ int      g_cnt[B];
__device__ uint32_t g_candi[B][CAND_CAP];
__device__ uint32_t g_anchor[B * NWORDS];
__device__ uint32_t g_dil[B * NWORDS];
__device__ int      g_prefix[B * NWORDS];
__device__ int      g_total[B];

// Monotone bijection float -> uint32 (ascending)
__device__ __forceinline__ uint32_t mono_key(float v) {
    uint32_t u = __float_as_uint(v);
    return (u & 0x80000000u) ? ~u : (u | 0x80000000u);
}

// Key for score = sigmoid(p) * m, in logit comparison domain.
__device__ __forceinline__ uint32_t score_key(float p, float m) {
    if (m == 1.0f) return mono_key(p);
    if (m == 0.0f) return mono_key(-CUDART_INF_F);
    float s = __fdividef(1.0f, 1.0f + __expf(-p)) * m;
    float pe;
    if (s <= 0.0f)      pe = -CUDART_INF_F;
    else if (s >= 1.0f) pe =  CUDART_INF_F;
    else                pe = __logf(s) - __logf(1.0f - s);
    return mono_key(pe);
}

// ---------------------------------------------------------------------------
// K1: keygen + 16-bit key store + private 2048-bin histogram (plain atomics).
// grid (CPB, B) x 256. No warp collectives in the hot loop.
// ---------------------------------------------------------------------------
__global__ __launch_bounds__(256) void k_hist(const float* __restrict__ pred,
                                              const float* __restrict__ mask)
{
    __shared__ uint32_t hist[2048];
    const int b = blockIdx.y, chunk = blockIdx.x, tid = threadIdx.x;
    for (int i = tid; i < 2048; i += 256) hist[i] = 0;
    __syncthreads();

    const float4* p4 = (const float4*)(pred + (size_t)b * HW) + chunk * CH4;
    const float4* m4 = (const float4*)(mask + (size_t)b * HW) + chunk * CH4;
    uint2*        k2 = (uint2*)(g_k16 + (size_t)b * HW / 2) + chunk * (CH4 / 2) * 2 / 2;
    // note: per chunk there are CHUNK/2 = 8000 packed words = 4000 uint2
    k2 = (uint2*)(g_k16 + (size_t)b * HW / 2 + (size_t)chunk * (CHUNK / 2));

    for (int v = tid; v < CH4; v += 256) {
        float4 pv = __ldcs(&p4[v]);
        float4 mv = __ldcs(&m4[v]);
        uint32_t k0 = score_key(pv.x, mv.x);
        uint32_t k1 = score_key(pv.y, mv.y);
        uint32_t kk2 = score_key(pv.z, mv.z);
        uint32_t k3 = score_key(pv.w, mv.w);
        uint2 pk;
        pk.x = (k0 >> 16) | (k1 & 0xFFFF0000u);
        pk.y = (kk2 >> 16) | (k3 & 0xFFFF0000u);
        __stcs(&k2[v], pk);
        atomicAdd(&hist[k0 >> 21], 1u);
        atomicAdd(&hist[k1 >> 21], 1u);
        atomicAdd(&hist[kk2 >> 21], 1u);
        atomicAdd(&hist[k3 >> 21], 1u);
    }
    __syncthreads();
    for (int i = tid; i < 2048; i += 256) g_histc[b][chunk][i] = hist[i];
}

// suffix-scan select on smem hist (blockDim must be 1024)
__device__ __forceinline__ void suffix_select(uint32_t* hist, int nbins, uint32_t remv,
                                              uint32_t* s_dig, uint32_t* s_rem)
{
    const int tid = threadIdx.x;
    for (int off = 1; off < nbins; off <<= 1) {
        int d0 = tid, d1 = tid + 1024;
        uint32_t v0 = 0, v1 = 0;
        if (d0 < nbins && d0 + off < nbins) v0 = hist[d0 + off];
        if (d1 < nbins && d1 + off < nbins) v1 = hist[d1 + off];
        __syncthreads();
        if (d0 < nbins) hist[d0] += v0;
        if (d1 < nbins) hist[d1] += v1;
        __syncthreads();
    }
    int d0 = tid, d1 = tid + 1024;
    if (d0 < nbins) {
        uint32_t ge = hist[d0], gt = (d0 + 1 < nbins) ? hist[d0 + 1] : 0u;
        if (ge >= remv && gt < remv) { *s_dig = (uint32_t)d0; *s_rem = remv - gt; }
    }
    if (d1 < nbins) {
        uint32_t ge = hist[d1], gt = (d1 + 1 < nbins) ? hist[d1 + 1] : 0u;
        if (ge >= remv && gt < remv) { *s_dig = (uint32_t)d1; *s_rem = remv - gt; }
    }
    __syncthreads();
}

// ---------------------------------------------------------------------------
// K2: sum chunk histograms, find round-1 pivot; zero candidate counter.
// grid B x 1024
// ---------------------------------------------------------------------------
__global__ __launch_bounds__(1024) void k_pivot()
{
    __shared__ uint32_t hist[2048];
    __shared__ uint32_t s_dig, s_rem;
    const int b = blockIdx.x, tid = threadIdx.x;
    uint32_t a0 = 0, a1 = 0;
    #pragma unroll
    for (int c = 0; c < CPB; c++) {
        a0 += g_histc[b][c][tid];
        a1 += g_histc[b][c][tid + 1024];
    }
    hist[tid] = a0; hist[tid + 1024] = a1;
    __syncthreads();
    suffix_select(hist, 2048, NA, &s_dig, &s_rem);
    if (tid == 0) { g_pivot[b] = make_uint2(s_dig, s_rem); g_cnt[b] = 0; }
}

// ---------------------------------------------------------------------------
// K3: classify 16-bit keys; anchors -> private smem bitmap slice (disjoint
// rows per chunk), candidates -> global list. grid (CPB, B) x 256.
// ---------------------------------------------------------------------------
__global__ __launch_bounds__(256) void k_mark()
{
    __shared__ uint32_t sbm[SLICE];
    const int b = blockIdx.y, chunk = blockIdx.x, tid = threadIdx.x;
    const uint32_t p1 = g_pivot[b].x;

    for (int w = tid; w < SLICE; w += 256) sbm[w] = 0;
    __syncthreads();

    const uint2* k2 = (const uint2*)(g_k16 + (size_t)b * HW / 2 + (size_t)chunk * (CHUNK / 2));
    const int ibase = chunk * CHUNK;          // first linear element of this chunk
    const int rbase = chunk * RPC;            // first row

    for (int v = tid; v < CH4; v += 256) {
        uint2 pk = __ldcs(&k2[v]);
        uint32_t ss[4] = { pk.x & 0xFFFFu, pk.x >> 16, pk.y & 0xFFFFu, pk.y >> 16 };
        #pragma unroll
        for (int j = 0; j < 4; j++) {
            uint32_t d = ss[j] >> 5;
            if (d >= p1) {
                int i = ibase + v * 4 + j;
                if (d > p1) {
                    int r = i / WW, c = i - r * WW;
                    atomicOr(&sbm[(r - rbase) * WPR + (c >> 5)], 1u << (c & 31));
                } else {
                    int slot = atomicAdd(&g_cnt[b], 1);
                    if (slot < CAND_CAP) g_candi[b][slot] = (uint32_t)i;
                }
            }
        }
    }
    __syncthreads();
    uint32_t* dst = g_anchor + b * NWORDS + rbase * WPR;
    for (int w = tid; w < SLICE; w += 256) dst[w] = sbm[w];
}

// ---------------------------------------------------------------------------
// K4: finisher — candidate key gather, radix rounds 2&3, tie resolve,
//     dilation, popcount prefix. grid B x 1024, dynamic smem.
//     layout: sbm[NWORDS] | hd[NWORDS] (hist aliases hd) | candk[CAND_CAP] | candi_s[CAND_CAP]
// ---------------------------------------------------------------------------
#define SMEM4_BYTES ((NWORDS + NWORDS + CAND_CAP + CAND_CAP) * 4)

__global__ __launch_bounds__(1024) void k_finish(const float* __restrict__ pred,
                                                 const float* __restrict__ mask)
{
    extern __shared__ uint32_t smem[];
    uint32_t* sbm    = smem;
    uint32_t* hd     = sbm + NWORDS;
    uint32_t* candk  = hd + NWORDS;
    uint32_t* candis = candk + CAND_CAP;
    uint32_t* hist   = hd;

    __shared__ uint32_t s_dig, s_rem;
    __shared__ int swarp[32];
    __shared__ int s_tot;

    const int b = blockIdx.x, tid = threadIdx.x, lane = tid & 31, wid = tid >> 5;
    const float* pb = pred + (size_t)b * HW;
    const float* mb = mask + (size_t)b * HW;
    const uint32_t p1 = g_pivot[b].x;
    uint32_t rem = g_pivot[b].y;
    const int nc = min(g_cnt[b], CAND_CAP);

    for (int w = tid; w < NWORDS; w += 1024) sbm[w] = g_anchor[b * NWORDS + w];
    for (int i = tid; i < 2048; i += 1024) hist[i] = 0;
    // gather candidate full keys
    for (int j = tid; j < nc; j += 1024) {
        uint32_t i = g_candi[b][j];
        candis[j] = i;
        candk[j] = score_key(__ldg(&pb[i]), __ldg(&mb[i]));
    }
    __syncthreads();

    // round 2: bits [10:21)
    for (int j = tid; j < nc; j += 1024) atomicAdd(&hist[(candk[j] >> 10) & 2047u], 1u);
    __syncthreads();
    suffix_select(hist, 2048, rem, &s_dig, &s_rem);
    const uint32_t d2 = s_dig; rem = s_rem;
    __syncthreads();

    // round 3: bits [0:10)
    hist[tid] = 0;
    __syncthreads();
    for (int j = tid; j < nc; j += 1024) {
        uint32_t k = candk[j];
        if (((k >> 10) & 2047u) == d2) atomicAdd(&hist[k & 1023u], 1u);
    }
    __syncthreads();
    suffix_select(hist, 1024, rem, &s_dig, &s_rem);
    const uint32_t K = (p1 << 21) | (d2 << 10) | s_dig;
    const uint32_t T = s_rem;
    __syncthreads();

    // mark candidate anchors (stable tie-break by ascending index)
    for (int j = tid; j < nc; j += 1024) {
        uint32_t k = candk[j];
        bool anc = false;
        if (k > K) anc = true;
        else if (k == K) {
            uint32_t myi = candis[j], rank = 0;
            for (int t = 0; t < nc; t++)
                if (candk[t] == K && candis[t] < myi) rank++;
            if (rank < T) anc = true;
        }
        if (anc) {
            int i = (int)candis[j];
            int r = i / WW, c = i - r * WW;
            atomicOr(&sbm[r * WPR + (c >> 5)], 1u << (c & 31));
        }
    }
    __syncthreads();

    // 5x5 dilation via bitwise shifts
    for (int w = tid; w < NWORDS; w += 1024) {
        int wi = w % WPR;
        uint32_t c    = sbm[w];
        uint32_t prev = (wi > 0)       ? sbm[w - 1] : 0u;
        uint32_t next = (wi < WPR - 1) ? sbm[w + 1] : 0u;
        uint32_t h = c | (c << 1) | (c << 2) | (c >> 1) | (c >> 2)
                   | (prev >> 31) | (prev >> 30) | (next << 31) | (next << 30);
        if (wi == WPR - 1) h &= 0xFFFFu;
        hd[w] = h;
    }
    __syncthreads();
    for (int w = tid; w < NWORDS; w += 1024) {
        int r = w / WPR;
        uint32_t vv = hd[w];
        if (r >= 1)   vv |= hd[w - WPR];
        if (r >= 2)   vv |= hd[w - 2 * WPR];
        if (r <= 398) vv |= hd[w + WPR];
        if (r <= 397) vv |= hd[w + 2 * WPR];
        sbm[w] = vv;
        g_dil[b * NWORDS + w] = vv;
    }
    __syncthreads();

    // exclusive prefix of word popcounts
    int running = 0;
    for (int base = 0; base < NWORDS; base += 1024) {
        int w = base + tid;
        int c = (w < NWORDS) ? __popc(sbm[w]) : 0;
        int v = c;
        for (int o = 1; o < 32; o <<= 1) { int n = __shfl_up_sync(0xffffffffu, v, o); if (lane >= o) v += n; }
        if (lane == 31) swarp[wid] = v;
        __syncthreads();
        if (wid == 0) {
            int t = swarp[lane], tv = t;
            for (int o = 1; o < 32; o <<= 1) { int n = __shfl_up_sync(0xffffffffu, tv, o); if (lane >= o) tv += n; }
            swarp[lane] = tv - t;
            if (lane == 31) s_tot = tv;
        }
        __syncthreads();
        if (w < NWORDS) g_prefix[b * NWORDS + w] = running + swarp[wid] + (v - c);
        running += s_tot;
        __syncthreads();
    }
    if (tid == 0) g_total[b] = running;
}

// ---------------------------------------------------------------------------
// k_write: one thread per element; streaming stores for all outputs.
// pos(i) = setrank(i) if set else S + (i - setrank(i))
// ---------------------------------------------------------------------------
__global__ __launch_bounds__(256) void k_write(const float* __restrict__ grid,
                                               const float* __restrict__ zs,
                                               float* __restrict__ out)
{
    const int b = blockIdx.y;
    const int i = blockIdx.x * 256 + threadIdx.x;
    if (i >= HW) return;

    const int r  = i / WW;
    const int c  = i - r * WW;
    const int w  = r * WPR + (c >> 5);
    const int bi = c & 31;

    const uint32_t bits = __ldg(&g_dil[b * NWORDS + w]);
    const int pre       = __ldg(&g_prefix[b * NWORDS + w]);
    const int S         = g_total[b];

    const bool set     = (bits >> bi) & 1u;
    const int  setrank = pre + __popc(bits & ((1u << bi) - 1u));
    const int  pos     = set ? setrank : S + (i - setrank);

    __stcs(&out[NM_OFF + (size_t)b * HW + i], (pos < NP) ? 1.0f : 0.0f);

    if (pos < NP) {
        __stcs(&out[OI_OFF + (size_t)b * NP + pos], (float)i);
        size_t xb = XY_OFF + ((size_t)b * NP + pos) * 2;
        __stcs(&out[xb],     (float)r);
        __stcs(&out[xb + 1], (float)c);
        float2 g = __ldg(&((const float2*)grid)[i]);
        float z0 = __ldg(&zs[0]), z1 = __ldg(&zs[1]), z2 = __ldg(&zs[2]), z3 = __ldg(&zs[3]);
        size_t qb = QP_OFF + (size_t)b * 240000 + (size_t)pos * 3;
        __stcs(&out[qb],          g.x); __stcs(&out[qb + 1],      g.y); __stcs(&out[qb + 2],      z0);
        __stcs(&out[qb + 60000],  g.x); __stcs(&out[qb + 60001],  g.y); __stcs(&out[qb + 60002],  z1);
        __stcs(&out[qb + 120000], g.x); __stcs(&out[qb + 120001], g.y); __stcs(&out[qb + 120002], z2);
        __stcs(&out[qb + 180000], g.x); __stcs(&out[qb + 180001], g.y); __stcs(&out[qb + 180002], z3);
    } else {
        __stcs(&out[IG_OFF + (size_t)b * NI + (pos - NP)], (float)i);
    }
}

// ---------------------------------------------------------------------------
extern "C" void kernel_launch(void* const* d_in, const int* in_sizes, int n_in,
                              void* d_out, int out_size)
{
    const float* pred = nullptr;
    const float* mask = nullptr;
    const float* grid = nullptr;
    const float* zs   = nullptr;
    for (int i = 0; i < n_in; i++) {
        if (in_sizes[i] == B * HW) {
            if (!pred) pred = (const float*)d_in[i];
            else if (!mask) mask = (const float*)d_in[i];
        } else if (in_sizes[i] == HW * 2) {
            grid = (const float*)d_in[i];
        } else if (in_sizes[i] == 4) {
            zs = (const float*)d_in[i];
        }
    }
    float* out = (float*)d_out;

    cudaFuncSetAttribute(k_finish, cudaFuncAttributeMaxDynamicSharedMemorySize, SMEM4_BYTES);

    dim3 gs(CPB, B);
    k_hist<<<gs, 256>>>(pred, mask);
    k_pivot<<<B, 1024>>>();
    k_mark<<<gs, 256>>>();
    k_finish<<<B, 1024, SMEM4_BYTES>>>(pred, mask);
    dim3 gw((HW + 255) / 256, B);
    k_write<<<gw, 256>>>(grid, zs, out);
}